// round 16
// baseline (speedup 1.0000x reference)
#include <cuda_runtime.h>
#include <cuda_fp16.h>
#include <cstdint>

// Problem constants: logits [B, 6, 512, 512] fp32, class_gt [B, 5] fp32, B=32.
#define NCLS   5
#define G      65536             // float4 groups per channel (512*512/4)
#define TPB    256
#define S_IMG  (G / TPB)         // 256 stages per image
#define NBJ    13                // blocks per image -> grid 416 <= 444 slots
#define MAXB   64

// Fixed-slot partials -> bitwise deterministic, no FP atomics, no zero-init.
__device__ float        g_part_s[MAXB * NBJ * NCLS];
__device__ float        g_part_c[MAXB * NBJ * NCLS];
__device__ unsigned int g_ticket;   // zero-init; last block resets each call

__device__ __forceinline__ float rcp_fast(float x)
{
    float y; asm("rcp.approx.ftz.f32 %0, %1;" : "=f"(y) : "f"(x)); return y;
}

__global__ void __launch_bounds__(TPB, 3)
apcl_fused_kernel(const float4* __restrict__ logits,
                  const float*  __restrict__ class_gt,
                  float*        __restrict__ out,
                  int B)
{
    const int b    = blockIdx.y;
    const int j    = blockIdx.x;
    const int t    = threadIdx.x;
    const int nblk = gridDim.x * gridDim.y;

    // This block's stage range within its image: [s0, s1), 19 or 20 stages.
    const int s0 = (j * S_IMG) / NBJ;
    const int s1 = ((j + 1) * S_IMG) / NBJ;
    const int n  = s1 - s0;

    const float4* src0 = logits + (size_t)b * 6 * G + (size_t)s0 * TPB + t;

    float s[NCLS];
#pragma unroll
    for (int c = 0; c < NCLS; c++) s[c] = 0.0f;
    unsigned cnt03 = 0;   // classes 0..3, 8 bits each (max 80/class fits)
    int      cnt4  = 0;

    const float L2E = 1.4426950408889634f;

    float4 v[3][NCLS];

#define PF(slot, st)                                                            \
    do {                                                                        \
        _Pragma("unroll")                                                       \
        for (int c = 0; c < NCLS; c++)                                          \
            v[slot][c] = __ldcg(src0 + (size_t)c * G + (st) * TPB);             \
    } while (0)

    // exps via ex2.approx.f16x2 (2 per MUFU). m is packed into the third
    // h2exp2 lane: monotone cvt/ex2/cvt => float(exp2h(m)) is EXACTLY the max
    // of the converted exps, so no separate emax reduction is needed.
    // argmax/tie mask stays in fp32 x-domain => identical semantics to ref.
#define CONSUME(slot)                                                           \
    do {                                                                        \
        const float4* cur = v[slot];                                            \
        _Pragma("unroll")                                                       \
        for (int l = 0; l < 4; l++) {                                           \
            float x[NCLS];                                                      \
            _Pragma("unroll")                                                   \
            for (int c = 0; c < NCLS; c++)                                      \
                x[c] = ((const float*)&cur[c])[l] * L2E;                        \
            const float m = fmaxf(fmaxf(fmaxf(x[0], x[1]),                      \
                                        fmaxf(x[2], x[3])), x[4]);              \
            __half2 e01 = h2exp2(__floats2half2_rn(x[0], x[1]));                \
            __half2 e23 = h2exp2(__floats2half2_rn(x[2], x[3]));                \
            __half2 e4m = h2exp2(__floats2half2_rn(x[4], m));                   \
            float2 f01 = __half22float2(e01);                                   \
            float2 f23 = __half22float2(e23);                                   \
            float2 f4m = __half22float2(e4m);                                   \
            const float sum  = (f01.x + f01.y) + (f23.x + f23.y) + f4m.x;       \
            const float emax = f4m.y;                                           \
            const float p = emax * rcp_fast(sum);                               \
            if (x[0] == m) { s[0] += p; cnt03 += 1u;       }                    \
            if (x[1] == m) { s[1] += p; cnt03 += 1u << 8;  }                    \
            if (x[2] == m) { s[2] += p; cnt03 += 1u << 16; }                    \
            if (x[3] == m) { s[3] += p; cnt03 += 1u << 24; }                    \
            if (x[4] == m) { s[4] += p; cnt4  += 1;        }                    \
        }                                                                       \
    } while (0)

    // Prologue: stages 0,1 in flight (n >= 19 always).
    PF(0, 0);
    PF(1, 1);

    // Main: triples with static ring slots (prefetch distance 2).
    int i = 0;
    for (; i + 3 <= n; i += 3) {
        PF(2, i + 2);
        CONSUME(0);
        if (i + 3 < n) PF(0, i + 3);
        CONSUME(1);
        if (i + 4 < n) PF(1, i + 4);
        CONSUME(2);
    }
    // Tail (0..2 stages); triple loop exits with i % 3 == 0 -> slots 0,1.
    if (i < n) { CONSUME(0); i++; }
    if (i < n) { CONSUME(1); }

#undef PF
#undef CONSUME

    float cf[NCLS];
    cf[0] = (float)( cnt03        & 255u);
    cf[1] = (float)((cnt03 >>  8) & 255u);
    cf[2] = (float)((cnt03 >> 16) & 255u);
    cf[3] = (float)((cnt03 >> 24) & 255u);
    cf[4] = (float)cnt4;

    // --- warp reduction (fixed order, deterministic) ---
#pragma unroll
    for (int off = 16; off > 0; off >>= 1) {
#pragma unroll
        for (int c = 0; c < NCLS; c++) {
            s[c]  += __shfl_down_sync(0xffffffffu, s[c],  off);
            cf[c] += __shfl_down_sync(0xffffffffu, cf[c], off);
        }
    }

    __shared__ float sw[TPB / 32][NCLS];
    __shared__ float cw[TPB / 32][NCLS];
    const int lane = t & 31;
    const int warp = t >> 5;
    if (lane == 0) {
#pragma unroll
        for (int c = 0; c < NCLS; c++) { sw[warp][c] = s[c]; cw[warp][c] = cf[c]; }
    }
    __syncthreads();

    if (t < NCLS) {
        float acc = 0.0f, ca = 0.0f;
#pragma unroll
        for (int w = 0; w < TPB / 32; w++) { acc += sw[w][t]; ca += cw[w][t]; }
        const int slot = (b * NBJ + j) * NCLS + t;
        g_part_s[slot] = acc;
        g_part_c[slot] = ca;
    }

    // --- last-block-done finalize (single launch) ---
    __shared__ int is_last;
    __threadfence();                       // partials visible before ticket
    if (t == 0) {
        unsigned int old = atomicAdd(&g_ticket, 1u);
        is_last = (old == (unsigned int)(nblk - 1)) ? 1 : 0;
    }
    __syncthreads();
    if (!is_last) return;

    // TPB-independent: each thread strides over all NT terms.
    float term = 0.0f;
    const int NT = B * NCLS;               // 160
    for (int idx = t; idx < NT; idx += TPB) {
        const int bb = idx / NCLS;
        const int cc = idx % NCLS;
        float S = 0.0f, N = 0.0f;
#pragma unroll
        for (int k = 0; k < NBJ; k++) {
            const int slot = (bb * NBJ + k) * NCLS + cc;
            S += __ldcg(&g_part_s[slot]);  // written by other SMs: bypass L1
            N += __ldcg(&g_part_c[slot]);
        }
        const float agg = (N > 0.0f) ? (S / N) : 0.0f;
        const float gt  = class_gt[idx];
        const float lp  = fmaxf(logf(agg),    -100.0f);  // log(0)=-inf -> -100
        const float l1  = fmaxf(log1pf(-agg), -100.0f);  // log1p(-1)=-inf -> -100
        term += gt * lp + (1.0f - gt) * l1;
    }

    __shared__ float red[TPB];
    red[t] = term;
    __syncthreads();
#pragma unroll
    for (int o = TPB / 2; o > 0; o >>= 1) {
        if (t < o) red[t] += red[t + o];
        __syncthreads();
    }
    if (t == 0) {
        out[0] = -red[0] / (float)NT;
        g_ticket = 0;                      // reset for next graph replay
    }
}

extern "C" void kernel_launch(void* const* d_in, const int* in_sizes, int n_in,
                              void* d_out, int out_size)
{
    // metadata order: segmentation_logits (large), class_gt (small).
    int li = 0, gi = 1;
    if (n_in >= 2 && in_sizes[1] > in_sizes[0]) { li = 1; gi = 0; }

    const float* logits = (const float*)d_in[li];
    const float* gt     = (const float*)d_in[gi];

    int B = in_sizes[gi] / NCLS;   // 32
    if (B < 1)    B = 1;
    if (B > MAXB) B = MAXB;

    dim3 grid(NBJ, B);             // 416 blocks for B=32: one full wave
    apcl_fused_kernel<<<grid, TPB>>>((const float4*)logits, gt, (float*)d_out, B);
}

// round 17
// speedup vs baseline: 1.0529x; 1.0529x over previous
#include <cuda_runtime.h>
#include <cuda_fp16.h>
#include <cstdint>

// Problem constants: logits [B, 6, 512, 512] fp32, class_gt [B, 5] fp32, B=32.
#define NCLS   5
#define G      65536             // float4 groups per channel (512*512/4)
#define TPB    256
#define S_IMG  (G / TPB)         // 256 stages per image
#define NBJ    13                // blocks per image -> grid 416 <= 444 slots
#define DEPTH  3                 // TMA ring depth (2 stages of fill slack)
#define MAXB   64

#define STAGE_F4     TPB                     // 256 float4 per channel per stage
#define STAGE_BYTES  (NCLS * STAGE_F4 * 16)  // 20480 B per stage

// Fixed-slot partials -> bitwise deterministic, no FP atomics, no zero-init.
__device__ float        g_part_s[MAXB * NBJ * NCLS];
__device__ float        g_part_c[MAXB * NBJ * NCLS];
__device__ unsigned int g_ticket;   // zero-init; last block resets each call

__device__ __forceinline__ float rcp_fast(float x)
{
    float y; asm("rcp.approx.ftz.f32 %0, %1;" : "=f"(y) : "f"(x)); return y;
}
__device__ __forceinline__ uint32_t smem_u32(const void* p)
{
    return (uint32_t)__cvta_generic_to_shared(p);
}
__device__ __forceinline__ void mbar_init(uint32_t addr, uint32_t count)
{
    asm volatile("mbarrier.init.shared.b64 [%0], %1;" :: "r"(addr), "r"(count) : "memory");
}
__device__ __forceinline__ void mbar_expect_tx(uint32_t addr, uint32_t bytes)
{
    asm volatile("mbarrier.arrive.expect_tx.shared.b64 _, [%0], %1;"
                 :: "r"(addr), "r"(bytes) : "memory");
}
__device__ __forceinline__ void mbar_wait(uint32_t addr, uint32_t parity)
{
    asm volatile(
        "{\n\t"
        ".reg .pred P;\n\t"
        "WAIT_%=:\n\t"
        "mbarrier.try_wait.parity.acquire.cta.shared::cta.b64 P, [%0], %1, 0x989680;\n\t"
        "@!P bra WAIT_%=;\n\t"
        "}"
        :: "r"(addr), "r"(parity) : "memory");
}
__device__ __forceinline__ void bulk_cp(uint32_t dst_smem, const void* src, uint32_t bytes,
                                        uint32_t mbar)
{
    asm volatile(
        "cp.async.bulk.shared::cta.global.mbarrier::complete_tx::bytes [%0], [%1], %2, [%3];"
        :: "r"(dst_smem), "l"(src), "r"(bytes), "r"(mbar) : "memory");
}

__global__ void __launch_bounds__(TPB, 3)
apcl_fused_kernel(const float4* __restrict__ logits,
                  const float*  __restrict__ class_gt,
                  float*        __restrict__ out,
                  int B)
{
    // DEPTH-deep TMA ring: [slot][channel][f4]. ~60 KB -> 3 blocks/SM.
    __shared__ float4   buf[DEPTH][NCLS][STAGE_F4];
    __shared__ uint64_t mbar_full[DEPTH];

    const int b    = blockIdx.y;
    const int j    = blockIdx.x;
    const int t    = threadIdx.x;
    const int nblk = gridDim.x * gridDim.y;

    // This block's stage range within its image: [s0, s1), 19 or 20 stages.
    const int s0 = (j * S_IMG) / NBJ;
    const int s1 = ((j + 1) * S_IMG) / NBJ;
    const int n  = s1 - s0;

    const float4* src0 = logits + (size_t)b * 6 * G + (size_t)s0 * TPB;

    if (t == 0) {
#pragma unroll
        for (int d = 0; d < DEPTH; d++)
            mbar_init(smem_u32(&mbar_full[d]), 1);
    }
    __syncthreads();

    // Prologue: fill slots 0..DEPTH-1 (n >= 19 > DEPTH always).
    if (t == 0) {
#pragma unroll
        for (int d = 0; d < DEPTH; d++) {
            const uint32_t mb = smem_u32(&mbar_full[d]);
            mbar_expect_tx(mb, STAGE_BYTES);
#pragma unroll
            for (int c = 0; c < NCLS; c++)
                bulk_cp(smem_u32(&buf[d][c][0]),
                        src0 + (size_t)c * G + d * STAGE_F4, STAGE_F4 * 16, mb);
        }
    }

    float s[NCLS];
#pragma unroll
    for (int c = 0; c < NCLS; c++) s[c] = 0.0f;
    unsigned cnt03 = 0;   // classes 0..3, 8 bits each (max 80/class fits)
    int      cnt4  = 0;

    const float L2E = 1.4426950408889634f;

    for (int st = 0; st < n; st++) {
        const int slot = st % DEPTH;
        const uint32_t mb = smem_u32(&mbar_full[slot]);
        mbar_wait(mb, (st / DEPTH) & 1);

        float4 v[NCLS];
#pragma unroll
        for (int c = 0; c < NCLS; c++)
            v[c] = buf[slot][c][t];        // conflict-free LDS.128

#pragma unroll
        for (int l = 0; l < 4; l++) {
            // exps via ex2.approx.f16x2 (2 per MUFU); m packed into third lane
            // (monotone cvt/ex2/cvt => exact emax). Tie mask in fp32 x-domain.
            float x[NCLS];
#pragma unroll
            for (int c = 0; c < NCLS; c++)
                x[c] = ((const float*)&v[c])[l] * L2E;
            const float m = fmaxf(fmaxf(fmaxf(x[0], x[1]),
                                        fmaxf(x[2], x[3])), x[4]);
            __half2 e01 = h2exp2(__floats2half2_rn(x[0], x[1]));
            __half2 e23 = h2exp2(__floats2half2_rn(x[2], x[3]));
            __half2 e4m = h2exp2(__floats2half2_rn(x[4], m));
            float2 f01 = __half22float2(e01);
            float2 f23 = __half22float2(e23);
            float2 f4m = __half22float2(e4m);
            const float sum  = (f01.x + f01.y) + (f23.x + f23.y) + f4m.x;
            const float p    = f4m.y * rcp_fast(sum);
            if (x[0] == m) { s[0] += p; cnt03 += 1u;       }
            if (x[1] == m) { s[1] += p; cnt03 += 1u << 8;  }
            if (x[2] == m) { s[2] += p; cnt03 += 1u << 16; }
            if (x[3] == m) { s[3] += p; cnt03 += 1u << 24; }
            if (x[4] == m) { s[4] += p; cnt4  += 1;        }
        }

        // All threads consumed this slot -> safe to refill for stage st+DEPTH.
        __syncthreads();
        if (t == 0 && st + DEPTH < n) {
            mbar_expect_tx(mb, STAGE_BYTES);
#pragma unroll
            for (int c = 0; c < NCLS; c++)
                bulk_cp(smem_u32(&buf[slot][c][0]),
                        src0 + (size_t)c * G + (st + DEPTH) * STAGE_F4,
                        STAGE_F4 * 16, mb);
        }
    }

    float cf[NCLS];
    cf[0] = (float)( cnt03        & 255u);
    cf[1] = (float)((cnt03 >>  8) & 255u);
    cf[2] = (float)((cnt03 >> 16) & 255u);
    cf[3] = (float)((cnt03 >> 24) & 255u);
    cf[4] = (float)cnt4;

    // --- warp reduction (fixed order, deterministic) ---
#pragma unroll
    for (int off = 16; off > 0; off >>= 1) {
#pragma unroll
        for (int c = 0; c < NCLS; c++) {
            s[c]  += __shfl_down_sync(0xffffffffu, s[c],  off);
            cf[c] += __shfl_down_sync(0xffffffffu, cf[c], off);
        }
    }

    __shared__ float sw[TPB / 32][NCLS];
    __shared__ float cw[TPB / 32][NCLS];
    const int lane = t & 31;
    const int warp = t >> 5;
    if (lane == 0) {
#pragma unroll
        for (int c = 0; c < NCLS; c++) { sw[warp][c] = s[c]; cw[warp][c] = cf[c]; }
    }
    __syncthreads();

    if (t < NCLS) {
        float acc = 0.0f, ca = 0.0f;
#pragma unroll
        for (int w = 0; w < TPB / 32; w++) { acc += sw[w][t]; ca += cw[w][t]; }
        const int slot = (b * NBJ + j) * NCLS + t;
        g_part_s[slot] = acc;
        g_part_c[slot] = ca;
    }

    // --- last-block-done finalize (single launch) ---
    __shared__ int is_last;
    __threadfence();                       // partials visible before ticket
    if (t == 0) {
        unsigned int old = atomicAdd(&g_ticket, 1u);
        is_last = (old == (unsigned int)(nblk - 1)) ? 1 : 0;
    }
    __syncthreads();
    if (!is_last) return;

    // TPB-independent: each thread strides over all NT terms.
    float term = 0.0f;
    const int NT = B * NCLS;               // 160
    for (int idx = t; idx < NT; idx += TPB) {
        const int bb = idx / NCLS;
        const int cc = idx % NCLS;
        float S = 0.0f, N = 0.0f;
#pragma unroll
        for (int k = 0; k < NBJ; k++) {
            const int slot = (bb * NBJ + k) * NCLS + cc;
            S += __ldcg(&g_part_s[slot]);  // written by other SMs: bypass L1
            N += __ldcg(&g_part_c[slot]);
        }
        const float agg = (N > 0.0f) ? (S / N) : 0.0f;
        const float gt  = class_gt[idx];
        const float lp  = fmaxf(logf(agg),    -100.0f);  // log(0)=-inf -> -100
        const float l1  = fmaxf(log1pf(-agg), -100.0f);  // log1p(-1)=-inf -> -100
        term += gt * lp + (1.0f - gt) * l1;
    }

    __shared__ float red[TPB];
    red[t] = term;
    __syncthreads();
#pragma unroll
    for (int o = TPB / 2; o > 0; o >>= 1) {
        if (t < o) red[t] += red[t + o];
        __syncthreads();
    }
    if (t == 0) {
        out[0] = -red[0] / (float)NT;
        g_ticket = 0;                      // reset for next graph replay
    }
}

extern "C" void kernel_launch(void* const* d_in, const int* in_sizes, int n_in,
                              void* d_out, int out_size)
{
    // metadata order: segmentation_logits (large), class_gt (small).
    int li = 0, gi = 1;
    if (n_in >= 2 && in_sizes[1] > in_sizes[0]) { li = 1; gi = 0; }

    const float* logits = (const float*)d_in[li];
    const float* gt     = (const float*)d_in[gi];

    int B = in_sizes[gi] / NCLS;   // 32
    if (B < 1)    B = 1;
    if (B > MAXB) B = MAXB;

    dim3 grid(NBJ, B);             // 416 blocks for B=32: one full wave
    apcl_fused_kernel<<<grid, TPB>>>((const float4*)logits, gt, (float*)d_out, B);
}